// round 17
// baseline (speedup 1.0000x reference)
#include <cuda_runtime.h>
#include <cstdint>
#include <cstddef>

// Single fused kernel, one launch.
// Phase 0: prefetch this block's 4 points of features into registers.
// Phase 1 (R14-validated cheap build): per-warp D build via lane-parallel
//          transcendentals + sparse stage chain in dedicated smem scratch.
// Phase 2: transform with FOUR stage buffers: stage 4 t's -> barrier ->
//          copy out 4 t's -> barrier. 8 barriers total (was 16), 4x deeper
//          store bursts between syncs.
__global__ __launch_bounds__(128) void fused_kernel(
        const float* __restrict__ feat,
        const float* __restrict__ q,
        const float* __restrict__ J1,
        const float* __restrict__ J2,
        float* __restrict__ out,
        int N, int T) {
    __shared__ float sStage[4 * 1408];   // 4 stage buffers; sF aliases [0,1920)
    __shared__ float sScr[768];          // build scratch: 4 warps x 192
    __shared__ float sD1[144];
    __shared__ float sD2[400];

    const int tid = threadIdx.x;
    const int lane = tid & 31;
    const int warp = tid >> 5;
    const int pbase = blockIdx.x * 4;

    // ---------------- Phase 0: feature prefetch into registers ----------------
    float4 pre[4];
    int npre = 0;
    {
        const float4* src = reinterpret_cast<const float4*>(feat + (size_t)pbase * 480);
#pragma unroll
        for (int it = 0; it < 4; it++) {
            int x = tid + it * 128;
            if (x < 480) { pre[it] = src[x]; npre = it + 1; }
        }
    }

    // ---------------- Phase 1: cheap cooperative D build ----------------
    {
        float* wscr = sScr + warp * 192;   // tables 4x32 [0,128), scrA@128, scrB@160
        const int t0 = 4 * warp;

        {   // (a) transcendentals + trig tables, 4 quats of this warp in parallel
            const int sg = lane >> 3;
            const int k  = lane & 7;
            const int t  = t0 + sg;
            if (t < T && k < 3) {
                float qr = __ldg(q + 4 * t + 0), qi = __ldg(q + 4 * t + 1);
                float qj = __ldg(q + 4 * t + 2), qk = __ldg(q + 4 * t + 3);
                float inv = rsqrtf(qr * qr + qi * qi + qj * qj + qk * qk);
                qr *= inv; qi *= inv; qj *= inv; qk *= inv;
                float two_s = 2.0f / (qr * qr + qi * qi + qj * qj + qk * qk);
                float M01 = two_s * (qi * qj - qk * qr);
                float M21 = two_s * (qj * qk + qi * qr);
                float M11 = 1.0f - two_s * (qi * qi + qk * qk);
                float M10 = two_s * (qi * qj + qk * qr);
                float M12 = two_s * (qj * qk - qi * qr);

                float ang;
                if (k == 1) {
                    ang = acosf(fmaxf(-1.0f, fminf(1.0f, M11)));
                } else {
                    float y = (k == 0) ? M01 : M10;
                    float x = (k == 0) ? M21 : -M12;
                    ang = atan2f(y, x);
                }
                float s1, c1;
                sincosf(ang, &s1, &c1);
                float c2 = fmaf(2.0f * c1, c1, -1.0f);
                float s2 = 2.0f * s1 * c1;

                float* tb = wscr + sg * 32 + k * 10;
                tb[0] = c2; tb[1] = c1; tb[2] = 1.0f; tb[3] = c1; tb[4] = c2;
                tb[5] = s2; tb[6] = s1; tb[7] = 0.0f; tb[8] = -s1; tb[9] = -s2;
            }
        }
        __syncwarp();

        // (b) stage chain, quat-sequential, lane = matrix entry
        float* scrA = wscr + 128;
        float* scrB = wscr + 160;
        const int i5 = lane / 5, j5 = lane % 5;
        const int i3 = lane / 3, j3 = lane % 3;

        for (int s = 0; s < 4; s++) {
            const int t = t0 + s;
            if (t >= T) break;
            const float* tab = wscr + s * 32;

            if (lane < 25)      // A = J2 @ Zb
                scrA[i5 * 5 + j5] =
                    __ldg(J2 + i5 * 5 + j5) * tab[10 + j5] -
                    __ldg(J2 + i5 * 5 + (4 - j5)) * tab[15 + j5];
            __syncwarp();
            if (lane < 25) {    // B = A @ J2
                float B = 0.0f;
#pragma unroll
                for (int k = 0; k < 5; k++)
                    B = fmaf(scrA[i5 * 5 + k], __ldg(J2 + k * 5 + j5), B);
                scrB[i5 * 5 + j5] = B;
            }
            __syncwarp();
            if (lane < 25)      // C = Za @ B
                scrA[i5 * 5 + j5] =
                    tab[i5] * scrB[i5 * 5 + j5] +
                    tab[5 + i5] * scrB[(4 - i5) * 5 + j5];
            __syncwarp();
            if (lane < 25)      // D = C @ Zg
                sD2[t * 25 + lane] =
                    scrA[i5 * 5 + j5] * tab[20 + j5] -
                    scrA[i5 * 5 + (4 - j5)] * tab[25 + j5];
            __syncwarp();

            if (lane < 9)
                scrA[i3 * 3 + j3] =
                    __ldg(J1 + i3 * 3 + j3) * tab[10 + j3 + 1] -
                    __ldg(J1 + i3 * 3 + (2 - j3)) * tab[15 + j3 + 1];
            __syncwarp();
            if (lane < 9) {
                float B = 0.0f;
#pragma unroll
                for (int k = 0; k < 3; k++)
                    B = fmaf(scrA[i3 * 3 + k], __ldg(J1 + k * 3 + j3), B);
                scrB[i3 * 3 + j3] = B;
            }
            __syncwarp();
            if (lane < 9)
                scrA[i3 * 3 + j3] =
                    tab[i3 + 1] * scrB[i3 * 3 + j3] +
                    tab[5 + i3 + 1] * scrB[(2 - i3) * 3 + j3];
            __syncwarp();
            if (lane < 9)
                sD1[t * 9 + lane] =
                    scrA[i3 * 3 + j3] * tab[20 + j3 + 1] -
                    scrA[i3 * 3 + (2 - j3)] * tab[25 + j3 + 1];
            __syncwarp();
        }
    }

    // ---------------- Phase 2: transform, 4 t's per barrier pair ----------------
    float* sF = sStage;
    {
        float4* dst = reinterpret_cast<float4*>(sF);
#pragma unroll
        for (int it = 0; it < 4; it++)
            if (it < npre) dst[tid + it * 128] = pre[it];
    }
    __syncthreads();

    // Register gather (all indices compile-time after unrolling).
    float4 f0[4];
    float in1[4][3];
    float in2[4][5];
    if (tid < 32) {
#pragma unroll
        for (int pp = 0; pp < 4; pp++)
            f0[pp] = reinterpret_cast<const float4*>(sF + pp * 480)[tid];
    } else if (tid < 96) {
        const int m = tid - 32;
#pragma unroll
        for (int pp = 0; pp < 4; pp++)
#pragma unroll
            for (int b = 0; b < 3; b++)
                in1[pp][b] = sF[pp * 480 + 128 + 3 * m + b];
    } else {
        const int m = tid - 96;
#pragma unroll
        for (int pp = 0; pp < 4; pp++)
#pragma unroll
            for (int b = 0; b < 5; b++)
                in2[pp][b] = sF[pp * 480 + 320 + 5 * m + b];
    }
    __syncthreads();   // sF reads done before first stage write

    for (int g = 0; g < 4; g++) {
        // ---- stage 4 t's into 4 buffers ----
        if (tid >= 32 && tid < 96) {
            const int m = tid - 32;
#pragma unroll
            for (int j = 0; j < 4; j++) {
                const int t = 4 * g + j;
                float* buf = sStage + j * 1408;
                const float* D = sD1 + t * 9;
#pragma unroll
                for (int a = 0; a < 3; a++) {
                    const float d0 = D[a * 3 + 0];
                    const float d1 = D[a * 3 + 1];
                    const float d2 = D[a * 3 + 2];
#pragma unroll
                    for (int pp = 0; pp < 4; pp++)
                        buf[pp * 352 + 3 * m + a] =
                            fmaf(d0, in1[pp][0], fmaf(d1, in1[pp][1], d2 * in1[pp][2]));
                }
            }
        } else if (tid >= 96) {
            const int m = tid - 96;
#pragma unroll
            for (int j = 0; j < 4; j++) {
                const int t = 4 * g + j;
                float* buf = sStage + j * 1408;
                const float* D = sD2 + t * 25;
#pragma unroll
                for (int a = 0; a < 5; a++) {
                    const float d0 = D[a * 5 + 0];
                    const float d1 = D[a * 5 + 1];
                    const float d2 = D[a * 5 + 2];
                    const float d3 = D[a * 5 + 3];
                    const float d4 = D[a * 5 + 4];
#pragma unroll
                    for (int pp = 0; pp < 4; pp++) {
                        float s = d0 * in2[pp][0];
                        s = fmaf(d1, in2[pp][1], s);
                        s = fmaf(d2, in2[pp][2], s);
                        s = fmaf(d3, in2[pp][3], s);
                        s = fmaf(d4, in2[pp][4], s);
                        buf[pp * 352 + 192 + 5 * m + a] = s;
                    }
                }
            }
        }
        __syncthreads();

        // ---- copy out 4 t's ----
#pragma unroll
        for (int j = 0; j < 4; j++) {
            const int t = 4 * g + j;
            float* buf = sStage + j * 1408;
            float* obase = out + ((size_t)t * N + pbase) * 480;
            if (tid < 32) {
#pragma unroll
                for (int pp = 0; pp < 4; pp++)
                    reinterpret_cast<float4*>(obase + pp * 480)[tid] = f0[pp];
            } else {
                for (int x = tid - 32; x < 352; x += 96) {
                    const int pp = x / 88;
                    const int c4 = x - pp * 88;
                    float4 v = reinterpret_cast<const float4*>(buf + pp * 352)[c4];
                    reinterpret_cast<float4*>(obase + pp * 480 + 128)[c4] = v;
                }
            }
        }
        __syncthreads();   // copy-outs done before next group's staging
    }
}

extern "C" void kernel_launch(void* const* d_in, const int* in_sizes, int n_in,
                              void* d_out, int out_size) {
    const float* feat = (const float*)d_in[0];
    const float* q    = (const float*)d_in[1];
    // d_in[2] = J0 (unused: l=0 is a pure broadcast in the reference)
    const float* J1   = (const float*)d_in[3];
    const float* J2   = (const float*)d_in[4];
    float* out = (float*)d_out;

    const int T = in_sizes[1] / 4;     // 16
    const int N = in_sizes[0] / 480;   // 16384

    fused_kernel<<<N / 4, 128>>>(feat, q, J1, J2, out, N, T);
}